// round 15
// baseline (speedup 1.0000x reference)
#include <cuda_runtime.h>
#include <cuda_bf16.h>
#include <cstdint>
#include <cstddef>

// ============================================================================
// PrecomputedMetaNet, mma.sync bf16 — round-14 champion + occ-3 step kernel.
//   prepass: fused single launch (converts + transpose + eye-check)
//   h     = relu(X @ W1^T + b1)             2-term, BN=64, S=2 (mm8)
//   coeff = h @ W2^T + b2                   fp32 warp GEMV
//   x_{j+1} = x_j + coeff[:,j]*(x_j @ M_j)  8 steps: step64 kernel,
//     BM=64 BN=128, 8 warps @ 32x32 tile, S=4, __launch_bounds__(256,3)
//     (acc halved -> ~82 regs -> 3 CTAs/SM -> 24 warps/SM latency hiding)
//   out   = x_8 @ Wp^T                      identity fast-path, else 3-term
// ============================================================================

#define B_  4096
#define D_  1024
#define H_  256
#define T_  8

// ---------------- device scratch (no cudaMalloc allowed) ----------------
__device__ __align__(16) __nv_bfloat16 g_task_hi[T_ * D_ * D_];
__device__ __align__(16) __nv_bfloat16 g_w1_hi[H_ * D_];
__device__ __align__(16) __nv_bfloat16 g_w1_lo[H_ * D_];
__device__ __align__(16) __nv_bfloat16 g_wp_hi[D_ * D_];
__device__ __align__(16) __nv_bfloat16 g_wp_lo[D_ * D_];
__device__ __align__(16) __nv_bfloat16 g_f_hi[B_ * D_];
__device__ __align__(16) __nv_bfloat16 g_f_lo[B_ * D_];
__device__ __align__(16) __nv_bfloat16 g_xh0[B_ * D_];
__device__ __align__(16) __nv_bfloat16 g_xh1[B_ * D_];
__device__ __align__(16) __nv_bfloat16 g_xl[B_ * D_];
__device__ __align__(16) float g_h[B_ * H_];
__device__ __align__(16) float g_coeff[B_ * T_];
__device__ __align__(16) float g_buf0[B_ * D_];
__device__ __align__(16) float g_buf1[B_ * D_];
__device__ int g_not_eye;

// ---------------- helpers ----------------
__device__ __forceinline__ uint32_t smem_u32(const void* p) {
    uint32_t a;
    asm("{ .reg .u64 t; cvta.to.shared.u64 t, %1; cvt.u32.u64 %0, t; }"
        : "=r"(a) : "l"(p));
    return a;
}

__device__ __forceinline__ void cp16(uint32_t dst, const void* src) {
    asm volatile("cp.async.cg.shared.global [%0], [%1], 16;"
                 :: "r"(dst), "l"(src) : "memory");
}

__device__ __forceinline__ void ldsm_x4(uint32_t& r0, uint32_t& r1,
                                        uint32_t& r2, uint32_t& r3, uint32_t addr) {
    asm volatile("ldmatrix.sync.aligned.m8n8.x4.shared.b16 {%0,%1,%2,%3}, [%4];"
                 : "=r"(r0), "=r"(r1), "=r"(r2), "=r"(r3) : "r"(addr));
}

__device__ __forceinline__ void mma_bf16(float* d, const uint32_t* a, const uint32_t* b) {
    asm volatile(
        "mma.sync.aligned.m16n8k16.row.col.f32.bf16.bf16.f32 "
        "{%0,%1,%2,%3},{%4,%5,%6,%7},{%8,%9},{%0,%1,%2,%3};"
        : "+f"(d[0]), "+f"(d[1]), "+f"(d[2]), "+f"(d[3])
        : "r"(a[0]), "r"(a[1]), "r"(a[2]), "r"(a[3]), "r"(b[0]), "r"(b[1]));
}

__device__ __forceinline__ uint32_t f2bf2(float x, float y) {
    __nv_bfloat162 t = __floats2bfloat162_rn(x, y);   // x -> low half
    return *reinterpret_cast<uint32_t*>(&t);
}

// ============================================================================
// step64: residual step, BM=64, BN=128, BK=32, S=4, 256 thr, 8 warps 2Mx4N
// (warp tile 32x32, acc=32 regs/thread), occ 3.
// out = Afp + coeff[:,cj] * (Ahi @ Bhi^T); WBF=1 bf16-hi copy, WBF=2 hi+lo
// (runtime-gated by wbfCond).
// ============================================================================
template <int WBF>
__global__ __launch_bounds__(256, 3)
void step64(const __nv_bfloat16* __restrict__ Ahi,
            const __nv_bfloat16* __restrict__ Bhi,
            const float* __restrict__ Afp,
            const float* __restrict__ coeff, int cj,
            float* __restrict__ out, __nv_bfloat16* __restrict__ outh,
            __nv_bfloat16* __restrict__ outl,
            const int* __restrict__ wbfCond,
            int M, int N, int K)
{
    extern __shared__ char smem[];
    constexpr int PITCH = 80;
    constexpr int TA = 64 * PITCH;             // 5120
    constexpr int TB = 128 * PITCH;            // 10240
    constexpr int STAGE = TA + TB;             // 15360
    constexpr int STAGES = 4;

    const int tid  = threadIdx.x;
    const int wid  = tid >> 5;
    const int lane = tid & 31;
    const int warp_m = (wid & 1) * 32;
    const int warp_n = (wid >> 1) * 32;
    const int bm = blockIdx.y * 64;
    const int bn = blockIdx.x * 128;
    const uint32_t su = smem_u32(smem);

    const uint32_t a_off = (lane & 15) * PITCH + ((lane >> 4) & 1) * 16;
    const uint32_t b_off = ((lane & 7) + ((lane >> 4) & 1) * 8) * PITCH
                         + ((lane >> 3) & 1) * 16;

    float acc[2][4][4];
#pragma unroll
    for (int mt = 0; mt < 2; mt++)
#pragma unroll
        for (int nt = 0; nt < 4; nt++)
#pragma unroll
            for (int q = 0; q < 4; q++) acc[mt][nt][q] = 0.0f;

    const int NT = K >> 5;

    auto load_stage = [&](int t, int s) {
        const int k0 = t << 5;
        const uint32_t base = su + (uint32_t)s * STAGE;
        // A: 64 rows x 4 chunks = 256 chunks, 1 per thread
        {
            int r = tid >> 2, c = tid & 3;
            uint32_t off = r * PITCH + c * 16;
            cp16(base + off, Ahi + (size_t)(bm + r) * K + k0 + c * 8);
        }
        // B: 128 rows x 4 chunks = 512 chunks, 2 per thread
#pragma unroll
        for (int it = 0; it < 2; ++it) {
            int idx = it * 256 + tid;
            int r = idx >> 2, c = idx & 3;
            uint32_t off = r * PITCH + c * 16;
            cp16(base + TA + off, Bhi + (size_t)(bn + r) * K + k0 + c * 8);
        }
        asm volatile("cp.async.commit_group;" ::: "memory");
    };

#pragma unroll
    for (int s = 0; s < STAGES - 1; ++s) load_stage(s, s);

    for (int t = 0; t < NT; ++t) {
        asm volatile("cp.async.wait_group %0;" :: "n"(STAGES - 2));
        __syncthreads();

        const uint32_t sa = su + (uint32_t)(t % STAGES) * STAGE;
        const uint32_t sb = sa + TA;

#pragma unroll
        for (int ks = 0; ks < 2; ++ks) {
            uint32_t ah[2][4];
#pragma unroll
            for (int mt = 0; mt < 2; mt++) {
                uint32_t base = (warp_m + mt * 16) * PITCH + a_off + ks * 32;
                ldsm_x4(ah[mt][0], ah[mt][1], ah[mt][2], ah[mt][3], sa + base);
            }
            uint32_t bh[4][2];
#pragma unroll
            for (int g = 0; g < 2; g++) {
                uint32_t base = (warp_n + g * 16) * PITCH + b_off + ks * 32;
                ldsm_x4(bh[2 * g][0], bh[2 * g][1], bh[2 * g + 1][0],
                        bh[2 * g + 1][1], sb + base);
            }
#pragma unroll
            for (int mt = 0; mt < 2; mt++)
#pragma unroll
                for (int nt = 0; nt < 4; nt++)
                    mma_bf16(acc[mt][nt], ah[mt], bh[nt]);
        }

        int tn = t + STAGES - 1;
        if (tn < NT) load_stage(tn, tn % STAGES);
        else asm volatile("cp.async.commit_group;" ::: "memory");
    }

    const bool doWbf = (WBF == 1) || (!wbfCond || *wbfCond != 0);

    // ---- epilogue: out = Afp + cr*acc ----
#pragma unroll
    for (int mt = 0; mt < 2; mt++) {
        int row0 = bm + warp_m + mt * 16 + (lane >> 2);
        int row1 = row0 + 8;
        float cr0 = coeff[row0 * T_ + cj];
        float cr1 = coeff[row1 * T_ + cj];
#pragma unroll
        for (int nt = 0; nt < 4; nt++) {
            int col = bn + warp_n + nt * 8 + (lane & 3) * 2;
            float2 b0 = *(const float2*)(Afp + (size_t)row0 * N + col);
            float2 b1 = *(const float2*)(Afp + (size_t)row1 * N + col);
            float2 v0 = make_float2(b0.x + cr0 * acc[mt][nt][0],
                                    b0.y + cr0 * acc[mt][nt][1]);
            float2 v1 = make_float2(b1.x + cr1 * acc[mt][nt][2],
                                    b1.y + cr1 * acc[mt][nt][3]);
            *(float2*)(out + (size_t)row0 * N + col) = v0;
            *(float2*)(out + (size_t)row1 * N + col) = v1;
            if (doWbf) {
                uint32_t h0 = f2bf2(v0.x, v0.y);
                uint32_t h1 = f2bf2(v1.x, v1.y);
                *(uint32_t*)(outh + (size_t)row0 * N + col) = h0;
                *(uint32_t*)(outh + (size_t)row1 * N + col) = h1;
                if (WBF == 2) {
                    __nv_bfloat162 hh0 = *reinterpret_cast<__nv_bfloat162*>(&h0);
                    __nv_bfloat162 hh1 = *reinterpret_cast<__nv_bfloat162*>(&h1);
                    uint32_t lo0 = f2bf2(v0.x - __bfloat162float(hh0.x),
                                         v0.y - __bfloat162float(hh0.y));
                    uint32_t lo1 = f2bf2(v1.x - __bfloat162float(hh1.x),
                                         v1.y - __bfloat162float(hh1.y));
                    *(uint32_t*)(outl + (size_t)row0 * N + col) = lo0;
                    *(uint32_t*)(outl + (size_t)row1 * N + col) = lo1;
                }
            }
        }
    }
}

// ============================================================================
// mm8: generic GEMM for metanet / projection (unchanged champion config).
// BM=128, BN_=64, BK=32, 256 threads, 8 warps (4M x 2N), warp tile 32x32.
// ============================================================================
template <int BN_, int NTERMS, int EPI, int STAGES>
__global__ __launch_bounds__(256, 2)
void mm8(const __nv_bfloat16* __restrict__ Ahi, const __nv_bfloat16* __restrict__ Alo,
         const __nv_bfloat16* __restrict__ Bhi, const __nv_bfloat16* __restrict__ Blo,
         const float* __restrict__ bias,
         float* __restrict__ out,
         const int* __restrict__ skipflag,
         int M, int N, int K)
{
    if (skipflag && *skipflag == 0) return;

    extern __shared__ char smem[];
    constexpr int PITCH = 80;
    constexpr int TA = 128 * PITCH;
    constexpr int TB = BN_ * PITCH;
    constexpr int NAA = (NTERMS >= 2) ? 2 : 1;
    constexpr int NBB = (NTERMS == 3) ? 2 : 1;
    constexpr int STAGE = NAA * TA + NBB * TB;
    constexpr int NTN = BN_ / 16;
    constexpr int NGB = NTN / 2;
    constexpr int ITB = (BN_ * 4) / 256;

    const int tid  = threadIdx.x;
    const int wid  = tid >> 5;
    const int lane = tid & 31;
    const int warp_m = (wid & 3) * 32;
    const int warp_n = (wid >> 2) * (BN_ / 2);
    const int bm = blockIdx.y * 128;
    const int bn = blockIdx.x * BN_;
    const uint32_t su = smem_u32(smem);

    const uint32_t a_off = (lane & 15) * PITCH + ((lane >> 4) & 1) * 16;
    const uint32_t b_off = ((lane & 7) + ((lane >> 4) & 1) * 8) * PITCH
                         + ((lane >> 3) & 1) * 16;

    float acc[2][NTN][4];
#pragma unroll
    for (int mt = 0; mt < 2; mt++)
#pragma unroll
        for (int nt = 0; nt < NTN; nt++)
#pragma unroll
            for (int q = 0; q < 4; q++) acc[mt][nt][q] = 0.0f;

    const int NT = K >> 5;

    auto load_stage = [&](int t, int s) {
        const int k0 = t << 5;
        const uint32_t base = su + (uint32_t)s * STAGE;
#pragma unroll
        for (int it = 0; it < 2; ++it) {
            int idx = it * 256 + tid;
            int r = idx >> 2, c = idx & 3;
            uint32_t off = r * PITCH + c * 16;
            size_t ga = (size_t)(bm + r) * K + k0 + c * 8;
            cp16(base + off, Ahi + ga);
            if (NTERMS >= 2) cp16(base + TA + off, Alo + ga);
        }
#pragma unroll
        for (int it = 0; it < ITB; ++it) {
            int idx = it * 256 + tid;
            int r = idx >> 2, c = idx & 3;
            uint32_t off = r * PITCH + c * 16;
            size_t gb = (size_t)(bn + r) * K + k0 + c * 8;
            cp16(base + NAA * TA + off, Bhi + gb);
            if (NTERMS == 3) cp16(base + NAA * TA + TB + off, Blo + gb);
        }
        asm volatile("cp.async.commit_group;" ::: "memory");
    };

#pragma unroll
    for (int s = 0; s < STAGES - 1; ++s) load_stage(s, s);

    for (int t = 0; t < NT; ++t) {
        asm volatile("cp.async.wait_group %0;" :: "n"(STAGES - 2));
        __syncthreads();

        const uint32_t sbuf = su + (uint32_t)(t % STAGES) * STAGE;
        const uint32_t sa  = sbuf;
        const uint32_t sal = sbuf + TA;
        const uint32_t sb  = sbuf + NAA * TA;
        const uint32_t sbl = sb + TB;

#pragma unroll
        for (int ks = 0; ks < 2; ++ks) {
            uint32_t ah[2][4], al[2][4];
#pragma unroll
            for (int mt = 0; mt < 2; mt++) {
                uint32_t base = (warp_m + mt * 16) * PITCH + a_off + ks * 32;
                ldsm_x4(ah[mt][0], ah[mt][1], ah[mt][2], ah[mt][3], sa + base);
                if (NTERMS >= 2)
                    ldsm_x4(al[mt][0], al[mt][1], al[mt][2], al[mt][3], sal + base);
            }
            uint32_t bh[NTN][2], bl[NTN][2];
#pragma unroll
            for (int g = 0; g < NGB; g++) {
                uint32_t base = (warp_n + g * 16) * PITCH + b_off + ks * 32;
                ldsm_x4(bh[2 * g][0], bh[2 * g][1], bh[2 * g + 1][0],
                        bh[2 * g + 1][1], sb + base);
                if (NTERMS == 3)
                    ldsm_x4(bl[2 * g][0], bl[2 * g][1], bl[2 * g + 1][0],
                            bl[2 * g + 1][1], sbl + base);
            }
#pragma unroll
            for (int mt = 0; mt < 2; mt++)
#pragma unroll
                for (int nt = 0; nt < NTN; nt++) {
                    mma_bf16(acc[mt][nt], ah[mt], bh[nt]);
                    if (NTERMS >= 2) mma_bf16(acc[mt][nt], al[mt], bh[nt]);
                    if (NTERMS == 3) mma_bf16(acc[mt][nt], ah[mt], bl[nt]);
                }
        }

        int tn = t + STAGES - 1;
        if (tn < NT) load_stage(tn, tn % STAGES);
        else asm volatile("cp.async.commit_group;" ::: "memory");
    }

#pragma unroll
    for (int mt = 0; mt < 2; mt++) {
        int row0 = bm + warp_m + mt * 16 + (lane >> 2);
        int row1 = row0 + 8;
#pragma unroll
        for (int nt = 0; nt < NTN; nt++) {
            int col = bn + warp_n + nt * 8 + (lane & 3) * 2;
            float2 v0 = make_float2(acc[mt][nt][0], acc[mt][nt][1]);
            float2 v1 = make_float2(acc[mt][nt][2], acc[mt][nt][3]);
            if (EPI == 1) {
                float2 bv = *(const float2*)(bias + col);
                v0.x = fmaxf(v0.x + bv.x, 0.0f);
                v0.y = fmaxf(v0.y + bv.y, 0.0f);
                v1.x = fmaxf(v1.x + bv.x, 0.0f);
                v1.y = fmaxf(v1.y + bv.y, 0.0f);
            }
            *(float2*)(out + (size_t)row0 * N + col) = v0;
            *(float2*)(out + (size_t)row1 * N + col) = v1;
        }
    }
}

// ============================================================================
// Fused prepass: one launch, blockIdx.x-ranged.
//   [0, 8192)     : task transpose tiles (32x32), j = bid>>10
//   [8192, 12288) : features split (float4/thread)
//   [12288,12544) : W1 split
//   [12544,13568) : Wp split + eye check
// ============================================================================
#define NB_TRANS 8192
#define NB_FEAT  4096
#define NB_W1    256
#define NB_WP    1024

__global__ __launch_bounds__(256)
void prepass(const float* __restrict__ features, const float* __restrict__ W1,
             const float* __restrict__ Wp, const float* __restrict__ task,
             __nv_bfloat16* __restrict__ fhi, __nv_bfloat16* __restrict__ flo,
             __nv_bfloat16* __restrict__ w1hi, __nv_bfloat16* __restrict__ w1lo,
             __nv_bfloat16* __restrict__ wphi, __nv_bfloat16* __restrict__ wplo,
             __nv_bfloat16* __restrict__ thi, int* __restrict__ flag)
{
    __shared__ float tile[32][33];
    const int bid = blockIdx.x;
    const int tid = threadIdx.x;

    if (bid < NB_TRANS) {
        int j = bid >> 10;
        int rem = bid & 1023;
        int n0 = (rem & 31) * 32, k0 = (rem >> 5) * 32;
        const float* src = task + (size_t)j * D_ * D_;
        int tx = tid & 7, ty = tid >> 3;
        float4 v = *(const float4*)(src + (size_t)(k0 + ty) * D_ + n0 + tx * 4);
        tile[ty][tx * 4 + 0] = v.x;
        tile[ty][tx * 4 + 1] = v.y;
        tile[ty][tx * 4 + 2] = v.z;
        tile[ty][tx * 4 + 3] = v.w;
        __syncthreads();
        int r = tid >> 3, q = tid & 7;
        uint32_t p0 = f2bf2(tile[q * 4 + 0][r], tile[q * 4 + 1][r]);
        uint32_t p1 = f2bf2(tile[q * 4 + 2][r], tile[q * 4 + 3][r]);
        size_t o = (size_t)j * D_ * D_ + (size_t)(n0 + r) * D_ + k0 + q * 4;
        *(uint2*)(thi + o) = make_uint2(p0, p1);
        return;
    }

    const float* in;
    __nv_bfloat16 *hi, *lo;
    int i;
    bool eye = false;
    if (bid < NB_TRANS + NB_FEAT) {
        in = features; hi = fhi; lo = flo;
        i = (bid - NB_TRANS) * 256 + tid;
    } else if (bid < NB_TRANS + NB_FEAT + NB_W1) {
        in = W1; hi = w1hi; lo = w1lo;
        i = (bid - NB_TRANS - NB_FEAT) * 256 + tid;
    } else {
        in = Wp; hi = wphi; lo = wplo; eye = true;
        i = (bid - NB_TRANS - NB_FEAT - NB_W1) * 256 + tid;
    }

    float4 v = ((const float4*)in)[i];
    uint32_t h0 = f2bf2(v.x, v.y), h1 = f2bf2(v.z, v.w);
    __nv_bfloat162 hh0 = *reinterpret_cast<__nv_bfloat162*>(&h0);
    __nv_bfloat162 hh1 = *reinterpret_cast<__nv_bfloat162*>(&h1);
    uint32_t l0 = f2bf2(v.x - __bfloat162float(hh0.x),
                        v.y - __bfloat162float(hh0.y));
    uint32_t l1 = f2bf2(v.z - __bfloat162float(hh1.x),
                        v.w - __bfloat162float(hh1.y));
    ((uint2*)hi)[i] = make_uint2(h0, h1);
    ((uint2*)lo)[i] = make_uint2(l0, l1);

    if (eye) {
        int e0 = i * 4;
        int r = e0 >> 10;
        int c = e0 & 1023;
        bool bad = (v.x != ((c + 0 == r) ? 1.0f : 0.0f)) |
                   (v.y != ((c + 1 == r) ? 1.0f : 0.0f)) |
                   (v.z != ((c + 2 == r) ? 1.0f : 0.0f)) |
                   (v.w != ((c + 3 == r) ? 1.0f : 0.0f));
        if (__any_sync(0xFFFFFFFFu, bad) && (tid & 31) == 0)
            atomicOr(flag, 1);
    }
}

// coeff[i,t] = dot(h[i,:], W2[t,:]) + b2[t] ; one warp per row
__global__ __launch_bounds__(256)
void coeff_kernel(const float* __restrict__ h, const float* __restrict__ W2,
                  const float* __restrict__ b2, float* __restrict__ coeff)
{
    int w = threadIdx.x >> 5;
    int l = threadIdx.x & 31;
    int row = blockIdx.x * 8 + w;
    const float* hr = h + (size_t)row * H_;

    float acc[8];
#pragma unroll
    for (int t = 0; t < 8; t++) acc[t] = 0.0f;
    for (int k = l; k < H_; k += 32) {
        float hv = hr[k];
#pragma unroll
        for (int t = 0; t < 8; t++) acc[t] += hv * W2[t * H_ + k];
    }
#pragma unroll
    for (int t = 0; t < 8; t++)
#pragma unroll
        for (int o = 16; o > 0; o >>= 1)
            acc[t] += __shfl_xor_sync(0xFFFFFFFFu, acc[t], o);
    if (l == 0)
#pragma unroll
        for (int t = 0; t < 8; t++)
            coeff[row * 8 + t] = acc[t] + b2[t];
}

// ============================================================================
extern "C" void kernel_launch(void* const* d_in, const int* in_sizes, int n_in,
                              void* d_out, int out_size)
{
    const float* features = (const float*)d_in[0];
    const float* W1       = (const float*)d_in[1];
    const float* b1       = (const float*)d_in[2];
    const float* W2       = (const float*)d_in[3];
    const float* b2       = (const float*)d_in[4];
    const float* task     = (const float*)d_in[5];
    const float* Wp       = (const float*)d_in[6];
    float* out = (float*)d_out;

    __nv_bfloat16 *thi, *w1hi, *w1lo, *wphi, *wplo, *fhi, *flo, *xh0, *xh1, *xl;
    float *h, *coeff, *buf0, *buf1;
    int* notEye;
    cudaGetSymbolAddress((void**)&thi,  g_task_hi);
    cudaGetSymbolAddress((void**)&w1hi, g_w1_hi);
    cudaGetSymbolAddress((void**)&w1lo, g_w1_lo);
    cudaGetSymbolAddress((void**)&wphi, g_wp_hi);
    cudaGetSymbolAddress((void**)&wplo, g_wp_lo);
    cudaGetSymbolAddress((void**)&fhi,  g_f_hi);
    cudaGetSymbolAddress((void**)&flo,  g_f_lo);
    cudaGetSymbolAddress((void**)&xh0,  g_xh0);
    cudaGetSymbolAddress((void**)&xh1,  g_xh1);
    cudaGetSymbolAddress((void**)&xl,   g_xl);
    cudaGetSymbolAddress((void**)&h,     g_h);
    cudaGetSymbolAddress((void**)&coeff, g_coeff);
    cudaGetSymbolAddress((void**)&buf0,  g_buf0);
    cudaGetSymbolAddress((void**)&buf1,  g_buf1);
    cudaGetSymbolAddress((void**)&notEye, g_not_eye);

    // smem budgets (PITCH=80):
    //   step64 (BM=64,BN=128): stage = 15360; S=4 -> 61440 (occ 3: 184KB)
    //   2-term metanet (BN=64): stage = 25600; S=2 -> 51200 (occ 2)
    //   3-term proj (BN=64):    stage = 30720; S=2 -> 61440 (occ 2)
    constexpr int SMEM_STEP = 4 * 15360;    // 61440
    constexpr int SMEM_2T   = 2 * 25600;
    constexpr int SMEM_3T   = 2 * 30720;
    cudaFuncSetAttribute(mm8<64, 2, 1, 2>,
                         cudaFuncAttributeMaxDynamicSharedMemorySize, SMEM_2T);
    cudaFuncSetAttribute(mm8<64, 3, 0, 2>,
                         cudaFuncAttributeMaxDynamicSharedMemorySize, SMEM_3T);
    cudaFuncSetAttribute(step64<1>,
                         cudaFuncAttributeMaxDynamicSharedMemorySize, SMEM_STEP);
    cudaFuncSetAttribute(step64<2>,
                         cudaFuncAttributeMaxDynamicSharedMemorySize, SMEM_STEP);

    // ---- fused pre-pass (one launch) ----
    cudaMemsetAsync(notEye, 0, sizeof(int));
    prepass<<<NB_TRANS + NB_FEAT + NB_W1 + NB_WP, 256>>>(
        features, W1, Wp, task, fhi, flo, w1hi, w1lo, wphi, wplo, thi, notEye);

    // ---- metanet hidden: h = relu(X @ W1^T + b1), 2-term, BN=64, S=2 ----
    mm8<64, 2, 1, 2><<<dim3(H_ / 64, B_ / 128), 256, SMEM_2T>>>(
        fhi, flo, w1hi, nullptr, b1, h, nullptr, B_, H_, D_);

    // ---- coeff = h @ W2^T + b2 ----
    coeff_kernel<<<B_ / 8, 256>>>(h, W2, b2, coeff);

    // ---- 8 sequential steps: BM=64 BN=128 occ-3 step64 ----
    const float* curf = features;
    const __nv_bfloat16* curh = fhi;
    for (int j = 0; j < T_; ++j) {
        if (j < T_ - 1) {
            float* nf = (j & 1) ? buf1 : buf0;
            __nv_bfloat16* nh = (j & 1) ? xh1 : xh0;
            step64<1><<<dim3(D_ / 128, B_ / 64), 256, SMEM_STEP>>>(
                curh, thi + (size_t)j * D_ * D_, curf, coeff, j,
                nf, nh, nullptr, nullptr, B_, D_, D_);
            curf = nf; curh = nh;
        } else {
            step64<2><<<dim3(D_ / 128, B_ / 64), 256, SMEM_STEP>>>(
                curh, thi + (size_t)j * D_ * D_, curf, coeff, j,
                out, xh1, xl, notEye, B_, D_, D_);
            curh = xh1;
        }
    }

    // ---- projection: Wp==I -> d_out already exact; else 3-term GEMM ----
    mm8<64, 3, 0, 2><<<dim3(D_ / 64, B_ / 128), 256, SMEM_3T>>>(
        xh1, xl, wphi, wplo, nullptr, out, notEye, B_, D_, D_);
}

// round 16
// speedup vs baseline: 1.2845x; 1.2845x over previous
#include <cuda_runtime.h>
#include <cuda_bf16.h>
#include <cstdint>
#include <cstddef>

// ============================================================================
// PrecomputedMetaNet, mma.sync bf16 — round-14 champion + 1-term metanet.
//   prepass: fused single launch (hi converts + transpose + Wp hi/lo + eye)
//   h     = relu(X @ W1^T + b1)             1-term bf16, BN=64, S=3
//   coeff = h @ W2^T + b2                   fp32 warp GEMV
//   x_{j+1} = x_j + coeff[:,j]*(x_j @ M_j)  8 steps, 1-term bf16, BN=128, S=4
//   out   = x_8 @ Wp^T                      identity fast-path, else 3-term
// ============================================================================

#define B_  4096
#define D_  1024
#define H_  256
#define T_  8

// ---------------- device scratch (no cudaMalloc allowed) ----------------
__device__ __align__(16) __nv_bfloat16 g_task_hi[T_ * D_ * D_];
__device__ __align__(16) __nv_bfloat16 g_w1_hi[H_ * D_];
__device__ __align__(16) __nv_bfloat16 g_wp_hi[D_ * D_];
__device__ __align__(16) __nv_bfloat16 g_wp_lo[D_ * D_];
__device__ __align__(16) __nv_bfloat16 g_f_hi[B_ * D_];
__device__ __align__(16) __nv_bfloat16 g_xh0[B_ * D_];
__device__ __align__(16) __nv_bfloat16 g_xh1[B_ * D_];
__device__ __align__(16) __nv_bfloat16 g_xl[B_ * D_];
__device__ __align__(16) float g_h[B_ * H_];
__device__ __align__(16) float g_coeff[B_ * T_];
__device__ __align__(16) float g_buf0[B_ * D_];
__device__ __align__(16) float g_buf1[B_ * D_];
__device__ int g_not_eye;

// ---------------- helpers ----------------
__device__ __forceinline__ uint32_t smem_u32(const void* p) {
    uint32_t a;
    asm("{ .reg .u64 t; cvta.to.shared.u64 t, %1; cvt.u32.u64 %0, t; }"
        : "=r"(a) : "l"(p));
    return a;
}

__device__ __forceinline__ void cp16(uint32_t dst, const void* src) {
    asm volatile("cp.async.cg.shared.global [%0], [%1], 16;"
                 :: "r"(dst), "l"(src) : "memory");
}

__device__ __forceinline__ void ldsm_x4(uint32_t& r0, uint32_t& r1,
                                        uint32_t& r2, uint32_t& r3, uint32_t addr) {
    asm volatile("ldmatrix.sync.aligned.m8n8.x4.shared.b16 {%0,%1,%2,%3}, [%4];"
                 : "=r"(r0), "=r"(r1), "=r"(r2), "=r"(r3) : "r"(addr));
}

__device__ __forceinline__ void mma_bf16(float* d, const uint32_t* a, const uint32_t* b) {
    asm volatile(
        "mma.sync.aligned.m16n8k16.row.col.f32.bf16.bf16.f32 "
        "{%0,%1,%2,%3},{%4,%5,%6,%7},{%8,%9},{%0,%1,%2,%3};"
        : "+f"(d[0]), "+f"(d[1]), "+f"(d[2]), "+f"(d[3])
        : "r"(a[0]), "r"(a[1]), "r"(a[2]), "r"(a[3]), "r"(b[0]), "r"(b[1]));
}

__device__ __forceinline__ uint32_t f2bf2(float x, float y) {
    __nv_bfloat162 t = __floats2bfloat162_rn(x, y);   // x -> low half
    return *reinterpret_cast<uint32_t*>(&t);
}

// ============================================================================
// GEMM: BM=128, BN_ in {64,128}, BK=32. 256 threads, 8 warps (4M x 2N),
// warp tile 32 x (BN_/2). STAGES-deep cp.async ring, 1 barrier per K-tile.
// NTERMS: 1 = Ahi*Bhi; 3 = Ahi*Bhi + Alo*Bhi + Ahi*Blo.
// EPI: 0 plain; 1 relu(acc+bias[col]); 2 Afp[r,c] + coeff[r,cj]*acc (K==N).
// WOUT: write fp32 out.
// WBF: 1 = also write bf16-hi of result; 2 = write bf16 hi+lo
//      (WBF stores skipped at runtime when wbfCond && *wbfCond == 0).
// skipflag: if non-null and *skipflag==0, exit immediately.
// ============================================================================
template <int BN_, int NTERMS, int EPI, int WOUT, int WBF, int STAGES>
__global__ __launch_bounds__(256, 2)
void mm8(const __nv_bfloat16* __restrict__ Ahi, const __nv_bfloat16* __restrict__ Alo,
         const __nv_bfloat16* __restrict__ Bhi, const __nv_bfloat16* __restrict__ Blo,
         const float* __restrict__ Afp, const float* __restrict__ bias,
         const float* __restrict__ coeff, int cj,
         float* __restrict__ out, __nv_bfloat16* __restrict__ outh,
         __nv_bfloat16* __restrict__ outl,
         const int* __restrict__ skipflag, const int* __restrict__ wbfCond,
         int M, int N, int K)
{
    if (skipflag && *skipflag == 0) return;

    extern __shared__ char smem[];
    constexpr int PITCH = 80;                  // 32 bf16 (64B) + 16B pad
    constexpr int TA = 128 * PITCH;            // 10240
    constexpr int TB = BN_ * PITCH;
    constexpr int NAA = (NTERMS >= 2) ? 2 : 1; // A tiles (hi[,lo])
    constexpr int NBB = (NTERMS == 3) ? 2 : 1; // B tiles (hi[,lo])
    constexpr int STAGE = NAA * TA + NBB * TB;
    constexpr int NTN = BN_ / 16;              // n8 frags per warp
    constexpr int NGB = NTN / 2;               // 16-row B ldsm groups
    constexpr int ITB = (BN_ * 4) / 256;       // B 16B chunks per thread

    const int tid  = threadIdx.x;
    const int wid  = tid >> 5;
    const int lane = tid & 31;
    const int warp_m = (wid & 3) * 32;
    const int warp_n = (wid >> 2) * (BN_ / 2);
    const int bm = blockIdx.y * 128;
    const int bn = blockIdx.x * BN_;
    const uint32_t su = smem_u32(smem);

    const uint32_t a_off = (lane & 15) * PITCH + ((lane >> 4) & 1) * 16;
    const uint32_t b_off = ((lane & 7) + ((lane >> 4) & 1) * 8) * PITCH
                         + ((lane >> 3) & 1) * 16;

    float acc[2][NTN][4];
#pragma unroll
    for (int mt = 0; mt < 2; mt++)
#pragma unroll
        for (int nt = 0; nt < NTN; nt++)
#pragma unroll
            for (int q = 0; q < 4; q++) acc[mt][nt][q] = 0.0f;

    const int NT = K >> 5;

    auto load_stage = [&](int t, int s) {
        const int k0 = t << 5;
        const uint32_t base = su + (uint32_t)s * STAGE;
#pragma unroll
        for (int it = 0; it < 2; ++it) {               // A: 512 chunks
            int idx = it * 256 + tid;
            int r = idx >> 2, c = idx & 3;
            uint32_t off = r * PITCH + c * 16;
            size_t ga = (size_t)(bm + r) * K + k0 + c * 8;
            cp16(base + off, Ahi + ga);
            if (NTERMS >= 2) cp16(base + TA + off, Alo + ga);
        }
#pragma unroll
        for (int it = 0; it < ITB; ++it) {             // B: BN_*4 chunks
            int idx = it * 256 + tid;
            int r = idx >> 2, c = idx & 3;
            uint32_t off = r * PITCH + c * 16;
            size_t gb = (size_t)(bn + r) * K + k0 + c * 8;
            cp16(base + NAA * TA + off, Bhi + gb);
            if (NTERMS == 3) cp16(base + NAA * TA + TB + off, Blo + gb);
        }
        asm volatile("cp.async.commit_group;" ::: "memory");
    };

    // prologue: fill STAGES-1 stages
#pragma unroll
    for (int s = 0; s < STAGES - 1; ++s) load_stage(s, s);

    for (int t = 0; t < NT; ++t) {
        asm volatile("cp.async.wait_group %0;" :: "n"(STAGES - 2));
        __syncthreads();

        const uint32_t sbuf = su + (uint32_t)(t % STAGES) * STAGE;
        const uint32_t sa  = sbuf;
        const uint32_t sal = sbuf + TA;
        const uint32_t sb  = sbuf + NAA * TA;
        const uint32_t sbl = sb + TB;

#pragma unroll
        for (int ks = 0; ks < 2; ++ks) {
            uint32_t ah[2][4], al[2][4];
#pragma unroll
            for (int mt = 0; mt < 2; mt++) {
                uint32_t base = (warp_m + mt * 16) * PITCH + a_off + ks * 32;
                ldsm_x4(ah[mt][0], ah[mt][1], ah[mt][2], ah[mt][3], sa + base);
                if (NTERMS >= 2)
                    ldsm_x4(al[mt][0], al[mt][1], al[mt][2], al[mt][3], sal + base);
            }
            uint32_t bh[NTN][2], bl[NTN][2];
#pragma unroll
            for (int g = 0; g < NGB; g++) {
                uint32_t base = (warp_n + g * 16) * PITCH + b_off + ks * 32;
                ldsm_x4(bh[2 * g][0], bh[2 * g][1], bh[2 * g + 1][0],
                        bh[2 * g + 1][1], sb + base);
                if (NTERMS == 3)
                    ldsm_x4(bl[2 * g][0], bl[2 * g][1], bl[2 * g + 1][0],
                            bl[2 * g + 1][1], sbl + base);
            }
#pragma unroll
            for (int mt = 0; mt < 2; mt++)
#pragma unroll
                for (int nt = 0; nt < NTN; nt++) {
                    mma_bf16(acc[mt][nt], ah[mt], bh[nt]);
                    if (NTERMS >= 2) mma_bf16(acc[mt][nt], al[mt], bh[nt]);
                    if (NTERMS == 3) mma_bf16(acc[mt][nt], ah[mt], bl[nt]);
                }
        }

        int tn = t + STAGES - 1;
        if (tn < NT) load_stage(tn, tn % STAGES);
        else asm volatile("cp.async.commit_group;" ::: "memory");
    }

    const bool doWbf = (WBF != 0) && (!wbfCond || *wbfCond != 0);

    // ---- epilogue ----
#pragma unroll
    for (int mt = 0; mt < 2; mt++) {
        int row0 = bm + warp_m + mt * 16 + (lane >> 2);
        int row1 = row0 + 8;
        float cr0 = 0.0f, cr1 = 0.0f;
        if (EPI == 2) {
            cr0 = coeff[row0 * T_ + cj];
            cr1 = coeff[row1 * T_ + cj];
        }
#pragma unroll
        for (int nt = 0; nt < NTN; nt++) {
            int col = bn + warp_n + nt * 8 + (lane & 3) * 2;
            float2 v0 = make_float2(acc[mt][nt][0], acc[mt][nt][1]);
            float2 v1 = make_float2(acc[mt][nt][2], acc[mt][nt][3]);
            if (EPI == 1) {
                float2 bv = *(const float2*)(bias + col);
                v0.x = fmaxf(v0.x + bv.x, 0.0f);
                v0.y = fmaxf(v0.y + bv.y, 0.0f);
                v1.x = fmaxf(v1.x + bv.x, 0.0f);
                v1.y = fmaxf(v1.y + bv.y, 0.0f);
            } else if (EPI == 2) {
                float2 b0 = *(const float2*)(Afp + (size_t)row0 * K + col);
                float2 b1 = *(const float2*)(Afp + (size_t)row1 * K + col);
                v0.x = b0.x + cr0 * v0.x;
                v0.y = b0.y + cr0 * v0.y;
                v1.x = b1.x + cr1 * v1.x;
                v1.y = b1.y + cr1 * v1.y;
            }
            if (WOUT) {
                *(float2*)(out + (size_t)row0 * N + col) = v0;
                *(float2*)(out + (size_t)row1 * N + col) = v1;
            }
            if (WBF >= 1 && doWbf) {
                uint32_t h0 = f2bf2(v0.x, v0.y);
                uint32_t h1 = f2bf2(v1.x, v1.y);
                *(uint32_t*)(outh + (size_t)row0 * N + col) = h0;
                *(uint32_t*)(outh + (size_t)row1 * N + col) = h1;
                if (WBF == 2) {
                    __nv_bfloat162 hh0 = *reinterpret_cast<__nv_bfloat162*>(&h0);
                    __nv_bfloat162 hh1 = *reinterpret_cast<__nv_bfloat162*>(&h1);
                    uint32_t lo0 = f2bf2(v0.x - __bfloat162float(hh0.x),
                                         v0.y - __bfloat162float(hh0.y));
                    uint32_t lo1 = f2bf2(v1.x - __bfloat162float(hh1.x),
                                         v1.y - __bfloat162float(hh1.y));
                    *(uint32_t*)(outl + (size_t)row0 * N + col) = lo0;
                    *(uint32_t*)(outl + (size_t)row1 * N + col) = lo1;
                }
            }
        }
    }
}

// ============================================================================
// Fused prepass: one launch, blockIdx.x-ranged.
//   [0, 8192)     : task transpose tiles (32x32), j = bid>>10
//   [8192, 12288) : features hi convert (float4/thread)
//   [12288,12544) : W1 hi convert
//   [12544,13568) : Wp hi+lo convert + eye check
// ============================================================================
#define NB_TRANS 8192
#define NB_FEAT  4096
#define NB_W1    256
#define NB_WP    1024

__global__ __launch_bounds__(256)
void prepass(const float* __restrict__ features, const float* __restrict__ W1,
             const float* __restrict__ Wp, const float* __restrict__ task,
             __nv_bfloat16* __restrict__ fhi,
             __nv_bfloat16* __restrict__ w1hi,
             __nv_bfloat16* __restrict__ wphi, __nv_bfloat16* __restrict__ wplo,
             __nv_bfloat16* __restrict__ thi, int* __restrict__ flag)
{
    __shared__ float tile[32][33];
    const int bid = blockIdx.x;
    const int tid = threadIdx.x;

    if (bid < NB_TRANS) {
        int j = bid >> 10;
        int rem = bid & 1023;
        int n0 = (rem & 31) * 32, k0 = (rem >> 5) * 32;
        const float* src = task + (size_t)j * D_ * D_;
        int tx = tid & 7, ty = tid >> 3;
        float4 v = *(const float4*)(src + (size_t)(k0 + ty) * D_ + n0 + tx * 4);
        tile[ty][tx * 4 + 0] = v.x;
        tile[ty][tx * 4 + 1] = v.y;
        tile[ty][tx * 4 + 2] = v.z;
        tile[ty][tx * 4 + 3] = v.w;
        __syncthreads();
        int r = tid >> 3, q = tid & 7;
        uint32_t p0 = f2bf2(tile[q * 4 + 0][r], tile[q * 4 + 1][r]);
        uint32_t p1 = f2bf2(tile[q * 4 + 2][r], tile[q * 4 + 3][r]);
        size_t o = (size_t)j * D_ * D_ + (size_t)(n0 + r) * D_ + k0 + q * 4;
        *(uint2*)(thi + o) = make_uint2(p0, p1);
        return;
    }

    if (bid < NB_TRANS + NB_FEAT + NB_W1) {
        // hi-only convert for features / W1
        const float* in;
        __nv_bfloat16* hi;
        int i;
        if (bid < NB_TRANS + NB_FEAT) {
            in = features; hi = fhi;
            i = (bid - NB_TRANS) * 256 + tid;
        } else {
            in = W1; hi = w1hi;
            i = (bid - NB_TRANS - NB_FEAT) * 256 + tid;
        }
        float4 v = ((const float4*)in)[i];
        ((uint2*)hi)[i] = make_uint2(f2bf2(v.x, v.y), f2bf2(v.z, v.w));
        return;
    }

    // Wp: hi+lo + eye check
    int i = (bid - NB_TRANS - NB_FEAT - NB_W1) * 256 + tid;
    float4 v = ((const float4*)Wp)[i];
    uint32_t h0 = f2bf2(v.x, v.y), h1 = f2bf2(v.z, v.w);
    __nv_bfloat162 hh0 = *reinterpret_cast<__nv_bfloat162*>(&h0);
    __nv_bfloat162 hh1 = *reinterpret_cast<__nv_bfloat162*>(&h1);
    uint32_t l0 = f2bf2(v.x - __bfloat162float(hh0.x),
                        v.y - __bfloat162float(hh0.y));
    uint32_t l1 = f2bf2(v.z - __bfloat162float(hh1.x),
                        v.w - __bfloat162float(hh1.y));
    ((uint2*)wphi)[i] = make_uint2(h0, h1);
    ((uint2*)wplo)[i] = make_uint2(l0, l1);

    int e0 = i * 4;
    int r = e0 >> 10;
    int c = e0 & 1023;
    bool bad = (v.x != ((c + 0 == r) ? 1.0f : 0.0f)) |
               (v.y != ((c + 1 == r) ? 1.0f : 0.0f)) |
               (v.z != ((c + 2 == r) ? 1.0f : 0.0f)) |
               (v.w != ((c + 3 == r) ? 1.0f : 0.0f));
    if (__any_sync(0xFFFFFFFFu, bad) && (tid & 31) == 0)
        atomicOr(flag, 1);
}

// coeff[i,t] = dot(h[i,:], W2[t,:]) + b2[t] ; one warp per row
__global__ __launch_bounds__(256)
void coeff_kernel(const float* __restrict__ h, const float* __restrict__ W2,
                  const float* __restrict__ b2, float* __restrict__ coeff)
{
    int w = threadIdx.x >> 5;
    int l = threadIdx.x & 31;
    int row = blockIdx.x * 8 + w;
    const float* hr = h + (size_t)row * H_;

    float acc[8];
#pragma unroll
    for (int t = 0; t < 8; t++) acc[t] = 0.0f;
    for (int k = l; k < H_; k += 32) {
        float hv = hr[k];
#pragma unroll
        for (int t = 0; t < 8; t++) acc[t] += hv * W2[t * H_ + k];
    }
#pragma unroll
    for (int t = 0; t < 8; t++)
#pragma unroll
        for (int o = 16; o > 0; o >>= 1)
            acc[t] += __shfl_xor_sync(0xFFFFFFFFu, acc[t], o);
    if (l == 0)
#pragma unroll
        for (int t = 0; t < 8; t++)
            coeff[row * 8 + t] = acc[t] + b2[t];
}

// ============================================================================
extern "C" void kernel_launch(void* const* d_in, const int* in_sizes, int n_in,
                              void* d_out, int out_size)
{
    const float* features = (const float*)d_in[0];
    const float* W1       = (const float*)d_in[1];
    const float* b1       = (const float*)d_in[2];
    const float* W2       = (const float*)d_in[3];
    const float* b2       = (const float*)d_in[4];
    const float* task     = (const float*)d_in[5];
    const float* Wp       = (const float*)d_in[6];
    float* out = (float*)d_out;

    __nv_bfloat16 *thi, *w1hi, *wphi, *wplo, *fhi, *xh0, *xh1, *xl;
    float *h, *coeff, *buf0, *buf1;
    int* notEye;
    cudaGetSymbolAddress((void**)&thi,  g_task_hi);
    cudaGetSymbolAddress((void**)&w1hi, g_w1_hi);
    cudaGetSymbolAddress((void**)&wphi, g_wp_hi);
    cudaGetSymbolAddress((void**)&wplo, g_wp_lo);
    cudaGetSymbolAddress((void**)&fhi,  g_f_hi);
    cudaGetSymbolAddress((void**)&xh0,  g_xh0);
    cudaGetSymbolAddress((void**)&xh1,  g_xh1);
    cudaGetSymbolAddress((void**)&xl,   g_xl);
    cudaGetSymbolAddress((void**)&h,     g_h);
    cudaGetSymbolAddress((void**)&coeff, g_coeff);
    cudaGetSymbolAddress((void**)&buf0,  g_buf0);
    cudaGetSymbolAddress((void**)&buf1,  g_buf1);
    cudaGetSymbolAddress((void**)&notEye, g_not_eye);

    // smem budgets (PITCH=80):
    //   steps  (1-term, BN=128): stage = 20480; S=4 -> 81920  (occ 2)
    //   1-term metanet (BN=64):  stage = 15360; S=3 -> 46080  (occ 2)
    //   3-term proj (BN=64):     stage = 30720; S=2 -> 61440  (occ 2)
    constexpr int SMEM_STEP = 4 * 20480;
    constexpr int SMEM_1T   = 3 * 15360;
    constexpr int SMEM_3T   = 2 * 30720;
    cudaFuncSetAttribute(mm8<64, 1, 1, 1, 0, 3>,
                         cudaFuncAttributeMaxDynamicSharedMemorySize, SMEM_1T);
    cudaFuncSetAttribute(mm8<64, 3, 0, 1, 0, 2>,
                         cudaFuncAttributeMaxDynamicSharedMemorySize, SMEM_3T);
    cudaFuncSetAttribute(mm8<128, 1, 2, 1, 1, 4>,
                         cudaFuncAttributeMaxDynamicSharedMemorySize, SMEM_STEP);
    cudaFuncSetAttribute(mm8<128, 1, 2, 1, 2, 4>,
                         cudaFuncAttributeMaxDynamicSharedMemorySize, SMEM_STEP);

    // ---- fused pre-pass (one launch) ----
    cudaMemsetAsync(notEye, 0, sizeof(int));
    prepass<<<NB_TRANS + NB_FEAT + NB_W1 + NB_WP, 256>>>(
        features, W1, Wp, task, fhi, w1hi, wphi, wplo, thi, notEye);

    // ---- metanet hidden: h = relu(X @ W1^T + b1), 1-term, BN=64, S=3 ----
    mm8<64, 1, 1, 1, 0, 3><<<dim3(H_ / 64, B_ / 128), 256, SMEM_1T>>>(
        fhi, nullptr, w1hi, nullptr, nullptr, b1, nullptr, 0,
        h, nullptr, nullptr, nullptr, nullptr, B_, H_, D_);

    // ---- coeff = h @ W2^T + b2 ----
    coeff_kernel<<<B_ / 8, 256>>>(h, W2, b2, coeff);

    // ---- 8 sequential steps, 1-term bf16, BK=32, S=4 ----
    const float* curf = features;
    const __nv_bfloat16* curh = fhi;
    for (int j = 0; j < T_; ++j) {
        if (j < T_ - 1) {
            float* nf = (j & 1) ? buf1 : buf0;
            __nv_bfloat16* nh = (j & 1) ? xh1 : xh0;
            mm8<128, 1, 2, 1, 1, 4><<<dim3(D_ / 128, B_ / 128), 256, SMEM_STEP>>>(
                curh, nullptr, thi + (size_t)j * D_ * D_, nullptr,
                curf, nullptr, coeff, j, nf, nh, nullptr, nullptr, nullptr,
                B_, D_, D_);
            curf = nf; curh = nh;
        } else {
            // last step: fp32 into d_out; bf16 hi/lo only if projection runs
            mm8<128, 1, 2, 1, 2, 4><<<dim3(D_ / 128, B_ / 128), 256, SMEM_STEP>>>(
                curh, nullptr, thi + (size_t)j * D_ * D_, nullptr,
                curf, nullptr, coeff, j, out, xh1, xl, nullptr, notEye,
                B_, D_, D_);
            curh = xh1;
        }
    }

    // ---- projection: Wp==I -> d_out already exact; else 3-term GEMM ----
    mm8<64, 3, 0, 1, 0, 2><<<dim3(D_ / 64, B_ / 128), 256, SMEM_3T>>>(
        curh, xl, wphi, wplo, nullptr, nullptr, nullptr, 0,
        out, nullptr, nullptr, notEye, nullptr, B_, D_, D_);
}